// round 7
// baseline (speedup 1.0000x reference)
#include <cuda_runtime.h>
#include <cuda_bf16.h>

// DistortionLoss, O(N) via sorted prefix sums. One warp per ray, 4 elems/lane.
//
// R7 algebra: swap summation order on the cross term so only ONE prefix scan
// (of w) is needed:
//   pairwise = sum_i ws_i * (2*W_<i + w_i - W_tot),   ws_i = w_i*(z_i+z_{i+1})
//   loss     = inv * [ pairwise + (1/3)*sum_i w_i^2*(z_{i+1}-z_i) ]
// This kills the second shuffle-scan ladder and its register chains.
// Also: 128-thread CTAs (grid 2048) for finer scheduling granularity.
// z via aligned-quad loads + neighbor shuffle (R4 path, best measured).

#define FULL 0xFFFFFFFFu

__global__ void __launch_bounds__(128) distortion_loss_kernel(
    const float*  __restrict__ w,     // [R,128]
    const float*  __restrict__ z,     // [R,129]
    const float*  __restrict__ nearp, // [R]
    const float*  __restrict__ farp,  // [R]
    float* __restrict__ out)          // [R]
{
    const int ray  = (blockIdx.x * 128 + threadIdx.x) >> 5;
    const int lane = threadIdx.x & 31;

    // ---- aligned-quad z load ----
    const int e0 = ray * 129;          // first element of this row
    const int qa = e0 >> 2;            // first aligned quad overlapping the row
    const int r  = e0 & 3;             // misalignment, uniform across the warp

    const float4* zq = reinterpret_cast<const float4*>(z);
    const float4 q  = zq[qa + lane];   // own aligned quad
    const float4 qx = zq[qa + 32];     // 33rd quad (broadcast, 1 wavefront)

    const float4 w4 = reinterpret_cast<const float4*>(w + (size_t)ray * 128)[lane];
    const float nr = __ldg(nearp + ray);
    const float fr = __ldg(farp  + ray);

    // ---- reconstruct row elements 4l..4l+4 (warp-uniform branch on r) ----
    float z0, z1, z2, z3, z4;
    const bool last = (lane == 31);
    if (r == 0) {
        z0 = q.x; z1 = q.y; z2 = q.z; z3 = q.w;
        float nx = __shfl_down_sync(FULL, q.x, 1);
        z4 = last ? qx.x : nx;
    } else if (r == 1) {
        z0 = q.y; z1 = q.z; z2 = q.w;
        float nx = __shfl_down_sync(FULL, q.x, 1);
        float ny = __shfl_down_sync(FULL, q.y, 1);
        z3 = last ? qx.x : nx;
        z4 = last ? qx.y : ny;
    } else if (r == 2) {
        z0 = q.z; z1 = q.w;
        float nx = __shfl_down_sync(FULL, q.x, 1);
        float ny = __shfl_down_sync(FULL, q.y, 1);
        float nz = __shfl_down_sync(FULL, q.z, 1);
        z2 = last ? qx.x : nx;
        z3 = last ? qx.y : ny;
        z4 = last ? qx.z : nz;
    } else {
        z0 = q.w;
        float nx = __shfl_down_sync(FULL, q.x, 1);
        float ny = __shfl_down_sync(FULL, q.y, 1);
        float nz = __shfl_down_sync(FULL, q.z, 1);
        float nw = __shfl_down_sync(FULL, q.w, 1);
        z1 = last ? qx.x : nx;
        z2 = last ? qx.y : ny;
        z3 = last ? qx.z : nz;
        z4 = last ? qx.w : nw;
    }

    const float wv0 = w4.x, wv1 = w4.y, wv2 = w4.z, wv3 = w4.w;

    // s = z_k + z_{k+1};  ws = w*s
    const float s0 = z0 + z1, s1 = z1 + z2, s2 = z2 + z3, s3 = z3 + z4;
    const float ws0 = wv0 * s0, ws1 = wv1 * s1, ws2 = wv2 * s2, ws3 = wv3 * s3;

    // lane-local inclusive sums of w only
    const float cw1 = wv0 + wv1, cw2 = cw1 + wv2, tw = cw2 + wv3;

    // single warp inclusive scan of lane totals of w
    float pw = tw;
    #pragma unroll
    for (int off = 1; off < 32; off <<= 1) {
        const float aw = __shfl_up_sync(FULL, pw, off);
        if (lane >= off) pw += aw;
    }
    const float bw   = pw - tw;                    // exclusive base over lanes < lane
    const float wtot = __shfl_sync(FULL, pw, 31);  // total weight of the ray

    // pairwise term: sum_k ws_k * (2*W_<k + w_k - W_tot)
    const float b2 = 2.0f * bw - wtot;
    float acc;
    acc  = ws0 * (b2              + wv0);
    acc += ws1 * (b2 + 2.0f * wv0 + wv1);
    acc += ws2 * (b2 + 2.0f * cw1 + wv2);
    acc += ws3 * (b2 + 2.0f * cw2 + wv3);

    // (1/3) * w^2 * dz term
    float qq;
    qq  = wv0 * wv0 * (z1 - z0);
    qq += wv1 * wv1 * (z2 - z1);
    qq += wv2 * wv2 * (z3 - z2);
    qq += wv3 * wv3 * (z4 - z3);
    acc = fmaf(qq, (1.0f / 3.0f), acc);

    // butterfly warp reduction
    #pragma unroll
    for (int off = 16; off > 0; off >>= 1)
        acc += __shfl_xor_sync(FULL, acc, off);

    if (lane == 0)
        out[ray] = acc * __fdividef(1.0f, fr - nr);
}

extern "C" void kernel_launch(void* const* d_in, const int* in_sizes, int n_in,
                              void* d_out, int out_size)
{
    const float* w   = (const float*)d_in[0]; // weights [R,128,1]
    const float* z   = (const float*)d_in[1]; // z_vals  [R,129]
    const float* nr  = (const float*)d_in[2]; // near    [R,1]
    const float* fr  = (const float*)d_in[3]; // far     [R,1]
    float*       out = (float*)d_out;         // [R,1]

    const int R = in_sizes[0] / 128;          // 8192
    distortion_loss_kernel<<<R / 4, 128>>>(w, z, nr, fr, out);  // 4 rays / 128-thr CTA
}

// round 9
// speedup vs baseline: 1.1615x; 1.1615x over previous
#include <cuda_runtime.h>
#include <cuda_bf16.h>

// DistortionLoss, O(N) via sorted prefix sums. One warp per ray, 4 elems/lane.
//
// R8 = R4 launch shape (256-thr CTAs, grid 1024 — best wall time) +
//      R7 single-scan algebra (best kernel time):
//   pairwise = sum_k ws_k * (2*W_<k + w_k - W_tot),  ws_k = w_k*(z_k+z_{k+1})
//   loss     = inv * [ pairwise + (1/3)*sum_k w_k^2*(z_{k+1}-z_k) ]
// z via aligned-quad loads + neighbor shuffle; single shuffle-scan of w;
// butterfly reduce; fast reciprocal hoisted off the tail chain.

#define FULL 0xFFFFFFFFu

__global__ void __launch_bounds__(256) distortion_loss_kernel(
    const float*  __restrict__ w,     // [R,128]
    const float*  __restrict__ z,     // [R,129]
    const float*  __restrict__ nearp, // [R]
    const float*  __restrict__ farp,  // [R]
    float* __restrict__ out)          // [R]
{
    const int ray  = (blockIdx.x * 256 + threadIdx.x) >> 5;
    const int lane = threadIdx.x & 31;

    // ---- aligned-quad z load ----
    const int e0 = ray * 129;          // first element of this row
    const int qa = e0 >> 2;            // first aligned quad overlapping the row
    const int r  = e0 & 3;             // misalignment, uniform across the warp

    const float4* zq = reinterpret_cast<const float4*>(z);
    const float4 q  = zq[qa + lane];   // own aligned quad
    const float4 qx = zq[qa + 32];     // 33rd quad (broadcast, 1 wavefront)

    const float4 w4 = reinterpret_cast<const float4*>(w + (size_t)ray * 128)[lane];
    const float nr = __ldg(nearp + ray);
    const float fr = __ldg(farp  + ray);
    const float inv = __fdividef(1.0f, fr - nr);   // independent of scan; hoisted

    // ---- reconstruct row elements 4l..4l+4 (warp-uniform branch on r) ----
    float z0, z1, z2, z3, z4;
    const bool last = (lane == 31);
    if (r == 0) {
        z0 = q.x; z1 = q.y; z2 = q.z; z3 = q.w;
        float nx = __shfl_down_sync(FULL, q.x, 1);
        z4 = last ? qx.x : nx;
    } else if (r == 1) {
        z0 = q.y; z1 = q.z; z2 = q.w;
        float nx = __shfl_down_sync(FULL, q.x, 1);
        float ny = __shfl_down_sync(FULL, q.y, 1);
        z3 = last ? qx.x : nx;
        z4 = last ? qx.y : ny;
    } else if (r == 2) {
        z0 = q.z; z1 = q.w;
        float nx = __shfl_down_sync(FULL, q.x, 1);
        float ny = __shfl_down_sync(FULL, q.y, 1);
        float nz = __shfl_down_sync(FULL, q.z, 1);
        z2 = last ? qx.x : nx;
        z3 = last ? qx.y : ny;
        z4 = last ? qx.z : nz;
    } else {
        z0 = q.w;
        float nx = __shfl_down_sync(FULL, q.x, 1);
        float ny = __shfl_down_sync(FULL, q.y, 1);
        float nz = __shfl_down_sync(FULL, q.z, 1);
        float nw = __shfl_down_sync(FULL, q.w, 1);
        z1 = last ? qx.x : nx;
        z2 = last ? qx.y : ny;
        z3 = last ? qx.z : nz;
        z4 = last ? qx.w : nw;
    }

    const float wv0 = w4.x, wv1 = w4.y, wv2 = w4.z, wv3 = w4.w;

    // s = z_k + z_{k+1};  ws = w*s
    const float s0 = z0 + z1, s1 = z1 + z2, s2 = z2 + z3, s3 = z3 + z4;
    const float ws0 = wv0 * s0, ws1 = wv1 * s1, ws2 = wv2 * s2, ws3 = wv3 * s3;

    // lane-local inclusive sums of w only
    const float cw1 = wv0 + wv1, cw2 = cw1 + wv2, tw = cw2 + wv3;

    // single warp inclusive scan of lane totals of w
    float pw = tw;
    #pragma unroll
    for (int off = 1; off < 32; off <<= 1) {
        const float aw = __shfl_up_sync(FULL, pw, off);
        if (lane >= off) pw += aw;
    }
    const float bw   = pw - tw;                    // exclusive base over lanes < lane
    const float wtot = __shfl_sync(FULL, pw, 31);  // total ray weight

    // pairwise term: sum_k ws_k * (2*W_<k + w_k - W_tot)
    const float b2 = 2.0f * bw - wtot;
    float acc;
    acc  = ws0 * (b2              + wv0);
    acc += ws1 * (b2 + 2.0f * wv0 + wv1);
    acc += ws2 * (b2 + 2.0f * cw1 + wv2);
    acc += ws3 * (b2 + 2.0f * cw2 + wv3);

    // (1/3) * w^2 * dz term
    float qq;
    qq  = wv0 * wv0 * (z1 - z0);
    qq += wv1 * wv1 * (z2 - z1);
    qq += wv2 * wv2 * (z3 - z2);
    qq += wv3 * wv3 * (z4 - z3);
    acc = fmaf(qq, (1.0f / 3.0f), acc);

    // butterfly warp reduction
    #pragma unroll
    for (int off = 16; off > 0; off >>= 1)
        acc += __shfl_xor_sync(FULL, acc, off);

    if (lane == 0)
        out[ray] = acc * inv;
}

extern "C" void kernel_launch(void* const* d_in, const int* in_sizes, int n_in,
                              void* d_out, int out_size)
{
    const float* w   = (const float*)d_in[0]; // weights [R,128,1]
    const float* z   = (const float*)d_in[1]; // z_vals  [R,129]
    const float* nr  = (const float*)d_in[2]; // near    [R,1]
    const float* fr  = (const float*)d_in[3]; // far     [R,1]
    float*       out = (float*)d_out;         // [R,1]

    const int R = in_sizes[0] / 128;          // 8192
    distortion_loss_kernel<<<R / 8, 256>>>(w, z, nr, fr, out);  // 8 rays / 256-thr CTA
}